// round 3
// baseline (speedup 1.0000x reference)
#include <cuda_runtime.h>
#include <cuda_fp16.h>

// CapsuleLayer dynamic routing, GB300 (sm_103a).
// x[B=128][R=1152][Ci=8], W[C=10][R=1152][Ci=8][O=16], 3 routing iterations.
// out v: [C][B][1][1][O] = 20480 fp32.
//
// logits_t[c,b,r,o] = u[c,b,r,o]*A_t[c,b,o]; per iter per (c,b,o):
//   E = sum_r exp(u*A), S = sum_r u*exp(u*A), s = S/E.
// Iter 0: A=0 -> s0 = mean_r u (no exp pass needed).
// Squash: GLOBAL Frobenius norm, scale = sqrt(n2)/(1+n2).
// u stored fp16 (47.2 MB, L2-resident; errors average out over 1152-way sums).

#define BB 128
#define RR 1152
#define CI 8
#define CC 10
#define OO 16
#define U_ELEMS (CC * BB * RR * OO)   // 23,592,960 halfs (~47.2 MB)
#define S_ELEMS (CC * BB * OO)        // 20,480

__device__ __half g_u[U_ELEMS];
__device__ float  g_s[S_ELEMS];
__device__ float  g_A[S_ELEMS];
__device__ float  g_n2[4];

// ---------------------------------------------------------------------------
// GEMM: u[c][b][r][o] = sum_i x[b][r][i] * W[c][r][i][o], output fp16.
// grid (36 r-chunks, 10 c), 256 threads: (r 0..31, og 0..7) owns o0=2og,o0+1.
// Per-warp store: 128 B fully coalesced. Also zeroes g_n2.
// ---------------------------------------------------------------------------
#define RB 32
#define BT 32

__global__ __launch_bounds__(256, 4)
void gemm_kernel(const float* __restrict__ x, const float* __restrict__ W) {
    const int c     = blockIdx.y;
    const int rbase = blockIdx.x * RB;
    const int tid   = threadIdx.x;
    const int r     = tid >> 3;
    const int og    = tid & 7;
    const int o0    = og * 2;

    if (blockIdx.x == 0 && blockIdx.y == 0 && tid < 4) g_n2[tid] = 0.0f;

    float w0[CI], w1[CI];
    {
        const float* Wp = W + ((size_t)c * RR + rbase + r) * (CI * OO) + o0;
        #pragma unroll
        for (int i = 0; i < CI; i++) {
            w0[i] = Wp[i * OO];
            w1[i] = Wp[i * OO + 1];
        }
    }

    __shared__ float xs[BT][RB * CI];   // 32 KB

    for (int bt = 0; bt < BB; bt += BT) {
        __syncthreads();
        for (int v = tid; v < BT * RB * CI / 4; v += 256) {
            int b = v >> 6;
            int q = v & 63;
            const float4* src = (const float4*)(x + ((size_t)(bt + b) * RR + rbase) * CI);
            ((float4*)xs[b])[q] = src[q];
        }
        __syncthreads();

        #pragma unroll 4
        for (int b = 0; b < BT; b++) {
            float4 xa = *(const float4*)&xs[b][r * CI];
            float4 xb = *(const float4*)&xs[b][r * CI + 4];
            float acc0, acc1;
            acc0 = xa.x * w0[0];
            acc1 = xa.x * w1[0];
            acc0 = fmaf(xa.y, w0[1], acc0);  acc1 = fmaf(xa.y, w1[1], acc1);
            acc0 = fmaf(xa.z, w0[2], acc0);  acc1 = fmaf(xa.z, w1[2], acc1);
            acc0 = fmaf(xa.w, w0[3], acc0);  acc1 = fmaf(xa.w, w1[3], acc1);
            acc0 = fmaf(xb.x, w0[4], acc0);  acc1 = fmaf(xb.x, w1[4], acc1);
            acc0 = fmaf(xb.y, w0[5], acc0);  acc1 = fmaf(xb.y, w1[5], acc1);
            acc0 = fmaf(xb.z, w0[6], acc0);  acc1 = fmaf(xb.z, w1[6], acc1);
            acc0 = fmaf(xb.w, w0[7], acc0);  acc1 = fmaf(xb.w, w1[7], acc1);

            size_t uidx = (((size_t)c * BB + bt + b) * RR + rbase + r) * OO + o0;
            *(__half2*)&g_u[uidx] = __floats2half2_rn(acc0, acc1);
        }
    }
}

// ---------------------------------------------------------------------------
// Iteration 0 (softmax uniform): s0[c,b,o] = mean_r u; n2[0] += sum s0^2.
// grid 1280 (c*128+b), 256 threads = 128 r-groups x 2 o-halves (uint4=8 halfs).
// ---------------------------------------------------------------------------
__global__ __launch_bounds__(256, 8)
void mean_kernel() {
    const int blk = blockIdx.x;
    const int tid = threadIdx.x;
    const int og  = tid & 1;                    // o = og*8 + k
    const int rg  = tid >> 1;                   // 0..127
    const __half* __restrict__ ub = g_u + (size_t)blk * (RR * OO);

    float S[8];
    #pragma unroll
    for (int k = 0; k < 8; k++) S[k] = 0.0f;

    #pragma unroll 9
    for (int r = rg; r < RR; r += 128) {        // 9 iterations
        uint4 v = *(const uint4*)&ub[r * OO + og * 8];
        float2 f0 = __half22float2(*(__half2*)&v.x);
        float2 f1 = __half22float2(*(__half2*)&v.y);
        float2 f2 = __half22float2(*(__half2*)&v.z);
        float2 f3 = __half22float2(*(__half2*)&v.w);
        S[0] += f0.x; S[1] += f0.y; S[2] += f1.x; S[3] += f1.y;
        S[4] += f2.x; S[5] += f2.y; S[6] += f3.x; S[7] += f3.y;
    }

    #pragma unroll
    for (int off = 2; off <= 16; off <<= 1) {
        #pragma unroll
        for (int k = 0; k < 8; k++)
            S[k] += __shfl_xor_sync(0xffffffffu, S[k], off);
    }

    __shared__ float pS[8][16];
    const int warp = tid >> 5;
    const int lane = tid & 31;
    if (lane < 2) {
        #pragma unroll
        for (int k = 0; k < 8; k++) pS[warp][og * 8 + k] = S[k];
    }
    __syncthreads();

    if (tid < 16) {
        float s = 0.0f;
        #pragma unroll
        for (int w = 0; w < 8; w++) s += pS[w][tid];
        s *= (1.0f / RR);
        g_s[blk * OO + tid] = s;

        float q = s * s;
        q += __shfl_xor_sync(0x0000ffffu, q, 1);
        q += __shfl_xor_sync(0x0000ffffu, q, 2);
        q += __shfl_xor_sync(0x0000ffffu, q, 4);
        q += __shfl_xor_sync(0x0000ffffu, q, 8);
        if (tid == 0) atomicAdd(&g_n2[0], q);
    }
}

// ---------------------------------------------------------------------------
// Iterations t=1,2. Prologue applies previous squash (scale from n2[t-1]),
// maintains g_A. Main: E = sum_r exp(u*a), S = sum_r u*exp(u*a); s = S/E.
// ---------------------------------------------------------------------------
__global__ __launch_bounds__(256, 8)
void iter_kernel(int t) {
    const int blk = blockIdx.x;
    const int tid = threadIdx.x;
    const int og  = tid & 1;
    const int rg  = tid >> 1;
    const __half* __restrict__ ub = g_u + (size_t)blk * (RR * OO);

    __shared__ float sA[16];

    if (tid < 16) {
        float n2 = g_n2[t - 1];
        float sc = sqrtf(n2) / (1.0f + n2);
        float v  = sc * g_s[blk * OO + tid];
        float a;
        if (t == 1) {
            a = v;
            g_A[blk * OO + tid] = a;   // written at t=1, read only at t=2
        } else {
            a = g_A[blk * OO + tid] + v;
        }
        sA[tid] = a;
    }
    __syncthreads();

    float a[8];
    #pragma unroll
    for (int k = 0; k < 8; k++) a[k] = sA[og * 8 + k];

    float E[8], S[8];
    #pragma unroll
    for (int k = 0; k < 8; k++) { E[k] = 0.0f; S[k] = 0.0f; }

    #pragma unroll 9
    for (int r = rg; r < RR; r += 128) {        // 9 iterations
        uint4 v = *(const uint4*)&ub[r * OO + og * 8];
        float2 f0 = __half22float2(*(__half2*)&v.x);
        float2 f1 = __half22float2(*(__half2*)&v.y);
        float2 f2 = __half22float2(*(__half2*)&v.z);
        float2 f3 = __half22float2(*(__half2*)&v.w);
        float uv0 = f0.x, uv1 = f0.y, uv2 = f1.x, uv3 = f1.y;
        float uv4 = f2.x, uv5 = f2.y, uv6 = f3.x, uv7 = f3.y;
        float e0 = __expf(uv0 * a[0]); E[0] += e0; S[0] = fmaf(e0, uv0, S[0]);
        float e1 = __expf(uv1 * a[1]); E[1] += e1; S[1] = fmaf(e1, uv1, S[1]);
        float e2 = __expf(uv2 * a[2]); E[2] += e2; S[2] = fmaf(e2, uv2, S[2]);
        float e3 = __expf(uv3 * a[3]); E[3] += e3; S[3] = fmaf(e3, uv3, S[3]);
        float e4 = __expf(uv4 * a[4]); E[4] += e4; S[4] = fmaf(e4, uv4, S[4]);
        float e5 = __expf(uv5 * a[5]); E[5] += e5; S[5] = fmaf(e5, uv5, S[5]);
        float e6 = __expf(uv6 * a[6]); E[6] += e6; S[6] = fmaf(e6, uv6, S[6]);
        float e7 = __expf(uv7 * a[7]); E[7] += e7; S[7] = fmaf(e7, uv7, S[7]);
    }

    #pragma unroll
    for (int off = 2; off <= 16; off <<= 1) {
        #pragma unroll
        for (int k = 0; k < 8; k++) {
            E[k] += __shfl_xor_sync(0xffffffffu, E[k], off);
            S[k] += __shfl_xor_sync(0xffffffffu, S[k], off);
        }
    }

    __shared__ float pE[8][16], pS[8][16];
    const int warp = tid >> 5;
    const int lane = tid & 31;
    if (lane < 2) {
        #pragma unroll
        for (int k = 0; k < 8; k++) {
            pE[warp][og * 8 + k] = E[k];
            pS[warp][og * 8 + k] = S[k];
        }
    }
    __syncthreads();

    if (tid < 16) {
        float Et = 0.0f, St = 0.0f;
        #pragma unroll
        for (int w = 0; w < 8; w++) { Et += pE[w][tid]; St += pS[w][tid]; }
        float s = St / Et;
        g_s[blk * OO + tid] = s;

        float q = s * s;
        q += __shfl_xor_sync(0x0000ffffu, q, 1);
        q += __shfl_xor_sync(0x0000ffffu, q, 2);
        q += __shfl_xor_sync(0x0000ffffu, q, 4);
        q += __shfl_xor_sync(0x0000ffffu, q, 8);
        if (tid == 0) atomicAdd(&g_n2[t], q);
    }
}

// ---------------------------------------------------------------------------
__global__ __launch_bounds__(256)
void final_kernel(float* __restrict__ out) {
    int i = blockIdx.x * blockDim.x + threadIdx.x;
    if (i < S_ELEMS) {
        float n2 = g_n2[2];
        float sc = sqrtf(n2) / (1.0f + n2);
        out[i] = sc * g_s[i];
    }
}

// ---------------------------------------------------------------------------
extern "C" void kernel_launch(void* const* d_in, const int* in_sizes, int n_in,
                              void* d_out, int out_size) {
    const float* x = (const float*)d_in[0];   // [128][1152][8]
    const float* W = (const float*)d_in[1];   // [10][1152][8][16]
    float* out = (float*)d_out;               // [10][128][1][1][16]

    gemm_kernel<<<dim3(RR / RB, CC), 256>>>(x, W);
    mean_kernel<<<CC * BB, 256>>>();
    iter_kernel<<<CC * BB, 256>>>(1);
    iter_kernel<<<CC * BB, 256>>>(2);
    final_kernel<<<(S_ELEMS + 255) / 256, 256>>>(out);
}

// round 4
// speedup vs baseline: 1.2320x; 1.2320x over previous
#include <cuda_runtime.h>
#include <cuda_fp16.h>

// CapsuleLayer dynamic routing, GB300 (sm_103a).
// x[B=128][R=1152][Ci=8], W[C=10][R=1152][Ci=8][O=16], 3 routing iterations.
// out v: [C][B][1][1][O] = 20480 fp32.
//
// logits_t[c,b,r,o] = u[c,b,r,o]*A_t[c,b,o]; per iter per (c,b,o):
//   E = sum_r exp(u*A), S = sum_r u*exp(u*A), s = S/E.
// Iter 0: A=0 -> s0 = mean_r u. Squash: GLOBAL Frobenius norm.
// u stored fp16 (47.2 MB). Iter passes are latency-bound streams -> explicit
// 6-deep load batching per thread (MLP), 64-reg budget.

#define BB 128
#define RR 1152
#define CI 8
#define CC 10
#define OO 16
#define U_ELEMS (CC * BB * RR * OO)
#define S_ELEMS (CC * BB * OO)

__device__ __half g_u[U_ELEMS];
__device__ float  g_s[S_ELEMS];
__device__ float  g_A[S_ELEMS];
__device__ float  g_n2[4];

// ---------------------------------------------------------------------------
// GEMM: u[c][b][r][o] = sum_i x[b][r][i] * W[c][r][i][o], output fp16.
// ---------------------------------------------------------------------------
#define RB 32
#define BT 32

__global__ __launch_bounds__(256, 4)
void gemm_kernel(const float* __restrict__ x, const float* __restrict__ W) {
    const int c     = blockIdx.y;
    const int rbase = blockIdx.x * RB;
    const int tid   = threadIdx.x;
    const int r     = tid >> 3;
    const int og    = tid & 7;
    const int o0    = og * 2;

    if (blockIdx.x == 0 && blockIdx.y == 0 && tid < 4) g_n2[tid] = 0.0f;

    float w0[CI], w1[CI];
    {
        const float* Wp = W + ((size_t)c * RR + rbase + r) * (CI * OO) + o0;
        #pragma unroll
        for (int i = 0; i < CI; i++) {
            w0[i] = Wp[i * OO];
            w1[i] = Wp[i * OO + 1];
        }
    }

    __shared__ float xs[BT][RB * CI];   // 32 KB

    for (int bt = 0; bt < BB; bt += BT) {
        __syncthreads();
        for (int v = tid; v < BT * RB * CI / 4; v += 256) {
            int b = v >> 6;
            int q = v & 63;
            const float4* src = (const float4*)(x + ((size_t)(bt + b) * RR + rbase) * CI);
            ((float4*)xs[b])[q] = src[q];
        }
        __syncthreads();

        #pragma unroll 4
        for (int b = 0; b < BT; b++) {
            float4 xa = *(const float4*)&xs[b][r * CI];
            float4 xb = *(const float4*)&xs[b][r * CI + 4];
            float acc0, acc1;
            acc0 = xa.x * w0[0];
            acc1 = xa.x * w1[0];
            acc0 = fmaf(xa.y, w0[1], acc0);  acc1 = fmaf(xa.y, w1[1], acc1);
            acc0 = fmaf(xa.z, w0[2], acc0);  acc1 = fmaf(xa.z, w1[2], acc1);
            acc0 = fmaf(xa.w, w0[3], acc0);  acc1 = fmaf(xa.w, w1[3], acc1);
            acc0 = fmaf(xb.x, w0[4], acc0);  acc1 = fmaf(xb.x, w1[4], acc1);
            acc0 = fmaf(xb.y, w0[5], acc0);  acc1 = fmaf(xb.y, w1[5], acc1);
            acc0 = fmaf(xb.z, w0[6], acc0);  acc1 = fmaf(xb.z, w1[6], acc1);
            acc0 = fmaf(xb.w, w0[7], acc0);  acc1 = fmaf(xb.w, w1[7], acc1);

            size_t uidx = (((size_t)c * BB + bt + b) * RR + rbase + r) * OO + o0;
            *(__half2*)&g_u[uidx] = __floats2half2_rn(acc0, acc1);
        }
    }
}

// ---------------------------------------------------------------------------
// Shared per-block reduction epilogue: 4 o's per thread (og = tid&3),
// rg_local = lane>>2 in [0,8). Reduce over rg within warp, then across warps.
// ---------------------------------------------------------------------------
// Iteration 0: s0 = mean_r u; atomic n2[0] += sum s0^2.
// grid 1280 (c*128+b), 256 thr = 64 rg x 4 og. 18 r-steps, batched 6 deep.
// ---------------------------------------------------------------------------
__global__ __launch_bounds__(256, 4)
void mean_kernel() {
    const int blk = blockIdx.x;
    const int tid = threadIdx.x;
    const int og  = tid & 3;                    // o = og*4 + k
    const int rg  = tid >> 2;                   // 0..63
    const __half* __restrict__ ub = g_u + (size_t)blk * (RR * OO) + og * 4;

    float S0 = 0.f, S1 = 0.f, S2 = 0.f, S3 = 0.f;

    #pragma unroll
    for (int jj = 0; jj < 18; jj += 6) {
        uint2 v[6];
        #pragma unroll
        for (int j = 0; j < 6; j++)
            v[j] = *(const uint2*)&ub[(rg + (jj + j) * 64) * OO];
        #pragma unroll
        for (int j = 0; j < 6; j++) {
            float2 f0 = __half22float2(*(__half2*)&v[j].x);
            float2 f1 = __half22float2(*(__half2*)&v[j].y);
            S0 += f0.x; S1 += f0.y; S2 += f1.x; S3 += f1.y;
        }
    }

    #pragma unroll
    for (int off = 4; off <= 16; off <<= 1) {
        S0 += __shfl_xor_sync(0xffffffffu, S0, off);
        S1 += __shfl_xor_sync(0xffffffffu, S1, off);
        S2 += __shfl_xor_sync(0xffffffffu, S2, off);
        S3 += __shfl_xor_sync(0xffffffffu, S3, off);
    }

    __shared__ float pS[8][16];
    const int warp = tid >> 5;
    const int lane = tid & 31;
    if (lane < 4)
        *(float4*)&pS[warp][lane * 4] = make_float4(S0, S1, S2, S3);
    __syncthreads();

    if (tid < 16) {
        float s = 0.0f;
        #pragma unroll
        for (int w = 0; w < 8; w++) s += pS[w][tid];
        s *= (1.0f / RR);
        g_s[blk * OO + tid] = s;

        float q = s * s;
        q += __shfl_xor_sync(0x0000ffffu, q, 1);
        q += __shfl_xor_sync(0x0000ffffu, q, 2);
        q += __shfl_xor_sync(0x0000ffffu, q, 4);
        q += __shfl_xor_sync(0x0000ffffu, q, 8);
        if (tid == 0) atomicAdd(&g_n2[0], q);
    }
}

// ---------------------------------------------------------------------------
// Iterations t=1,2. Prologue applies previous squash; maintains g_A.
// Main: E = sum_r exp(u*a), S = sum_r u*exp(u*a); s = S/E; n2[t] += s^2.
// ---------------------------------------------------------------------------
__global__ __launch_bounds__(256, 4)
void iter_kernel(int t) {
    const int blk = blockIdx.x;
    const int tid = threadIdx.x;
    const int og  = tid & 3;
    const int rg  = tid >> 2;
    const __half* __restrict__ ub = g_u + (size_t)blk * (RR * OO) + og * 4;

    __shared__ float sA[16];

    if (tid < 16) {
        float n2 = g_n2[t - 1];
        float sc = sqrtf(n2) / (1.0f + n2);
        float v  = sc * g_s[blk * OO + tid];
        float a;
        if (t == 1) {
            a = v;
            g_A[blk * OO + tid] = a;   // written at t=1, read only at t=2
        } else {
            a = g_A[blk * OO + tid] + v;
        }
        sA[tid] = a;
    }
    __syncthreads();

    const float a0 = sA[og * 4 + 0];
    const float a1 = sA[og * 4 + 1];
    const float a2 = sA[og * 4 + 2];
    const float a3 = sA[og * 4 + 3];

    float E0 = 0.f, E1 = 0.f, E2 = 0.f, E3 = 0.f;
    float S0 = 0.f, S1 = 0.f, S2 = 0.f, S3 = 0.f;

    #pragma unroll
    for (int jj = 0; jj < 18; jj += 6) {
        uint2 v[6];
        #pragma unroll
        for (int j = 0; j < 6; j++)
            v[j] = *(const uint2*)&ub[(rg + (jj + j) * 64) * OO];
        #pragma unroll
        for (int j = 0; j < 6; j++) {
            float2 f0 = __half22float2(*(__half2*)&v[j].x);
            float2 f1 = __half22float2(*(__half2*)&v[j].y);
            float e0 = __expf(f0.x * a0); E0 += e0; S0 = fmaf(e0, f0.x, S0);
            float e1 = __expf(f0.y * a1); E1 += e1; S1 = fmaf(e1, f0.y, S1);
            float e2 = __expf(f1.x * a2); E2 += e2; S2 = fmaf(e2, f1.x, S2);
            float e3 = __expf(f1.y * a3); E3 += e3; S3 = fmaf(e3, f1.y, S3);
        }
    }

    #pragma unroll
    for (int off = 4; off <= 16; off <<= 1) {
        E0 += __shfl_xor_sync(0xffffffffu, E0, off);
        E1 += __shfl_xor_sync(0xffffffffu, E1, off);
        E2 += __shfl_xor_sync(0xffffffffu, E2, off);
        E3 += __shfl_xor_sync(0xffffffffu, E3, off);
        S0 += __shfl_xor_sync(0xffffffffu, S0, off);
        S1 += __shfl_xor_sync(0xffffffffu, S1, off);
        S2 += __shfl_xor_sync(0xffffffffu, S2, off);
        S3 += __shfl_xor_sync(0xffffffffu, S3, off);
    }

    __shared__ float pE[8][16], pS[8][16];
    const int warp = tid >> 5;
    const int lane = tid & 31;
    if (lane < 4) {
        *(float4*)&pE[warp][lane * 4] = make_float4(E0, E1, E2, E3);
        *(float4*)&pS[warp][lane * 4] = make_float4(S0, S1, S2, S3);
    }
    __syncthreads();

    if (tid < 16) {
        float Et = 0.0f, St = 0.0f;
        #pragma unroll
        for (int w = 0; w < 8; w++) { Et += pE[w][tid]; St += pS[w][tid]; }
        float s = St / Et;
        g_s[blk * OO + tid] = s;

        float q = s * s;
        q += __shfl_xor_sync(0x0000ffffu, q, 1);
        q += __shfl_xor_sync(0x0000ffffu, q, 2);
        q += __shfl_xor_sync(0x0000ffffu, q, 4);
        q += __shfl_xor_sync(0x0000ffffu, q, 8);
        if (tid == 0) atomicAdd(&g_n2[t], q);
    }
}

// ---------------------------------------------------------------------------
__global__ __launch_bounds__(256)
void final_kernel(float* __restrict__ out) {
    int i = blockIdx.x * blockDim.x + threadIdx.x;
    if (i < S_ELEMS) {
        float n2 = g_n2[2];
        float sc = sqrtf(n2) / (1.0f + n2);
        out[i] = sc * g_s[i];
    }
}

// ---------------------------------------------------------------------------
extern "C" void kernel_launch(void* const* d_in, const int* in_sizes, int n_in,
                              void* d_out, int out_size) {
    const float* x = (const float*)d_in[0];   // [128][1152][8]
    const float* W = (const float*)d_in[1];   // [10][1152][8][16]
    float* out = (float*)d_out;               // [10][128][1][1][16]

    gemm_kernel<<<dim3(RR / RB, CC), 256>>>(x, W);
    mean_kernel<<<CC * BB, 256>>>();
    iter_kernel<<<CC * BB, 256>>>(1);
    iter_kernel<<<CC * BB, 256>>>(2);
    final_kernel<<<(S_ELEMS + 255) / 256, 256>>>(out);
}

// round 5
// speedup vs baseline: 1.8855x; 1.5304x over previous
#include <cuda_runtime.h>
#include <cuda_fp16.h>

// CapsuleLayer dynamic routing, GB300 (sm_103a).
// x[B=128][R=1152][Ci=8], W[C=10][R=1152][Ci=8][O=16], 3 routing iterations.
// out v: [C][B][1][1][O] = 20480 fp32.
//
// logits_t[c,b,r,o] = u[c,b,r,o]*A_t[c,b,o]; per iter per (c,b,o):
//   E = sum_r exp(u*A), S = sum_r u*exp(u*A), s = S/E.
// Iter 0: A=0 -> s0 = mean_r u. Squash: GLOBAL Frobenius norm.
// u fp16 (47.2 MB). Iter/mean: 6-deep load batches inside a NON-unrolled
// 3-step outer loop (regs ~48 -> 5 CTAs/SM), exp via raw ex2 with log2e
// pre-folded into the per-(c,b,o) scalar.

#define BB 128
#define RR 1152
#define CI 8
#define CC 10
#define OO 16
#define U_ELEMS (CC * BB * RR * OO)
#define S_ELEMS (CC * BB * OO)
#define LOG2E 1.4426950408889634f

__device__ __half g_u[U_ELEMS];
__device__ float  g_s[S_ELEMS];
__device__ float  g_A[S_ELEMS];
__device__ float  g_n2[4];

__device__ __forceinline__ float ex2f(float x) {
    float r;
    asm("ex2.approx.f32 %0, %1;" : "=f"(r) : "f"(x));
    return r;
}

// ---------------------------------------------------------------------------
// GEMM: u[c][b][r][o] = sum_i x[b][r][i] * W[c][r][i][o], output fp16.
// ---------------------------------------------------------------------------
#define RB 32
#define BT 32

__global__ __launch_bounds__(256, 4)
void gemm_kernel(const float* __restrict__ x, const float* __restrict__ W) {
    const int c     = blockIdx.y;
    const int rbase = blockIdx.x * RB;
    const int tid   = threadIdx.x;
    const int r     = tid >> 3;
    const int og    = tid & 7;
    const int o0    = og * 2;

    if (blockIdx.x == 0 && blockIdx.y == 0 && tid < 4) g_n2[tid] = 0.0f;

    float w0[CI], w1[CI];
    {
        const float* Wp = W + ((size_t)c * RR + rbase + r) * (CI * OO) + o0;
        #pragma unroll
        for (int i = 0; i < CI; i++) {
            w0[i] = Wp[i * OO];
            w1[i] = Wp[i * OO + 1];
        }
    }

    __shared__ float xs[BT][RB * CI];   // 32 KB

    for (int bt = 0; bt < BB; bt += BT) {
        __syncthreads();
        for (int v = tid; v < BT * RB * CI / 4; v += 256) {
            int b = v >> 6;
            int q = v & 63;
            const float4* src = (const float4*)(x + ((size_t)(bt + b) * RR + rbase) * CI);
            ((float4*)xs[b])[q] = src[q];
        }
        __syncthreads();

        #pragma unroll 4
        for (int b = 0; b < BT; b++) {
            float4 xa = *(const float4*)&xs[b][r * CI];
            float4 xb = *(const float4*)&xs[b][r * CI + 4];
            float acc0, acc1;
            acc0 = xa.x * w0[0];
            acc1 = xa.x * w1[0];
            acc0 = fmaf(xa.y, w0[1], acc0);  acc1 = fmaf(xa.y, w1[1], acc1);
            acc0 = fmaf(xa.z, w0[2], acc0);  acc1 = fmaf(xa.z, w1[2], acc1);
            acc0 = fmaf(xa.w, w0[3], acc0);  acc1 = fmaf(xa.w, w1[3], acc1);
            acc0 = fmaf(xb.x, w0[4], acc0);  acc1 = fmaf(xb.x, w1[4], acc1);
            acc0 = fmaf(xb.y, w0[5], acc0);  acc1 = fmaf(xb.y, w1[5], acc1);
            acc0 = fmaf(xb.z, w0[6], acc0);  acc1 = fmaf(xb.z, w1[6], acc1);
            acc0 = fmaf(xb.w, w0[7], acc0);  acc1 = fmaf(xb.w, w1[7], acc1);

            size_t uidx = (((size_t)c * BB + bt + b) * RR + rbase + r) * OO + o0;
            *(__half2*)&g_u[uidx] = __floats2half2_rn(acc0, acc1);
        }
    }
}

// ---------------------------------------------------------------------------
// Iteration 0: s0 = mean_r u; atomic n2[0] += sum s0^2.
// grid 1280 (c*128+b), 256 thr = 64 rg x 4 og. 3 outer steps x 6-deep batch.
// ---------------------------------------------------------------------------
__global__ __launch_bounds__(256, 5)
void mean_kernel() {
    const int blk = blockIdx.x;
    const int tid = threadIdx.x;
    const int og  = tid & 3;
    const int rg  = tid >> 2;
    const __half* __restrict__ p =
        g_u + (size_t)blk * (RR * OO) + og * 4 + rg * OO;

    float S0 = 0.f, S1 = 0.f, S2 = 0.f, S3 = 0.f;

    for (int jj = 0; jj < 3; jj++) {
        uint2 v[6];
        #pragma unroll
        for (int j = 0; j < 6; j++)
            v[j] = *(const uint2*)(p + j * (64 * OO));
        p += 6 * 64 * OO;
        #pragma unroll
        for (int j = 0; j < 6; j++) {
            float2 f0 = __half22float2(*(__half2*)&v[j].x);
            float2 f1 = __half22float2(*(__half2*)&v[j].y);
            S0 += f0.x; S1 += f0.y; S2 += f1.x; S3 += f1.y;
        }
    }

    #pragma unroll
    for (int off = 4; off <= 16; off <<= 1) {
        S0 += __shfl_xor_sync(0xffffffffu, S0, off);
        S1 += __shfl_xor_sync(0xffffffffu, S1, off);
        S2 += __shfl_xor_sync(0xffffffffu, S2, off);
        S3 += __shfl_xor_sync(0xffffffffu, S3, off);
    }

    __shared__ float pS[8][16];
    const int warp = tid >> 5;
    const int lane = tid & 31;
    if (lane < 4)
        *(float4*)&pS[warp][lane * 4] = make_float4(S0, S1, S2, S3);
    __syncthreads();

    if (tid < 16) {
        float s = 0.0f;
        #pragma unroll
        for (int w = 0; w < 8; w++) s += pS[w][tid];
        s *= (1.0f / RR);
        g_s[blk * OO + tid] = s;

        float q = s * s;
        q += __shfl_xor_sync(0x0000ffffu, q, 1);
        q += __shfl_xor_sync(0x0000ffffu, q, 2);
        q += __shfl_xor_sync(0x0000ffffu, q, 4);
        q += __shfl_xor_sync(0x0000ffffu, q, 8);
        if (tid == 0) atomicAdd(&g_n2[0], q);
    }
}

// ---------------------------------------------------------------------------
// Iterations t=1,2. Prologue applies previous squash; maintains g_A.
// exp(u*a) computed as ex2(u * (a*log2e)).
// ---------------------------------------------------------------------------
__global__ __launch_bounds__(256, 5)
void iter_kernel(int t) {
    const int blk = blockIdx.x;
    const int tid = threadIdx.x;
    const int og  = tid & 3;
    const int rg  = tid >> 2;
    const __half* __restrict__ p =
        g_u + (size_t)blk * (RR * OO) + og * 4 + rg * OO;

    __shared__ float sA[16];

    if (tid < 16) {
        float n2 = g_n2[t - 1];
        float sc = sqrtf(n2) / (1.0f + n2);
        float v  = sc * g_s[blk * OO + tid];
        float a;
        if (t == 1) {
            a = v;
            g_A[blk * OO + tid] = a;   // written at t=1, read only at t=2
        } else {
            a = g_A[blk * OO + tid] + v;
        }
        sA[tid] = a * LOG2E;
    }
    __syncthreads();

    const float a0 = sA[og * 4 + 0];
    const float a1 = sA[og * 4 + 1];
    const float a2 = sA[og * 4 + 2];
    const float a3 = sA[og * 4 + 3];

    float E0 = 0.f, E1 = 0.f, E2 = 0.f, E3 = 0.f;
    float S0 = 0.f, S1 = 0.f, S2 = 0.f, S3 = 0.f;

    for (int jj = 0; jj < 3; jj++) {
        uint2 v[6];
        #pragma unroll
        for (int j = 0; j < 6; j++)
            v[j] = *(const uint2*)(p + j * (64 * OO));
        p += 6 * 64 * OO;
        #pragma unroll
        for (int j = 0; j < 6; j++) {
            float2 f0 = __half22float2(*(__half2*)&v[j].x);
            float2 f1 = __half22float2(*(__half2*)&v[j].y);
            float e0 = ex2f(f0.x * a0); E0 += e0; S0 = fmaf(e0, f0.x, S0);
            float e1 = ex2f(f0.y * a1); E1 += e1; S1 = fmaf(e1, f0.y, S1);
            float e2 = ex2f(f1.x * a2); E2 += e2; S2 = fmaf(e2, f1.x, S2);
            float e3 = ex2f(f1.y * a3); E3 += e3; S3 = fmaf(e3, f1.y, S3);
        }
    }

    #pragma unroll
    for (int off = 4; off <= 16; off <<= 1) {
        E0 += __shfl_xor_sync(0xffffffffu, E0, off);
        E1 += __shfl_xor_sync(0xffffffffu, E1, off);
        E2 += __shfl_xor_sync(0xffffffffu, E2, off);
        E3 += __shfl_xor_sync(0xffffffffu, E3, off);
        S0 += __shfl_xor_sync(0xffffffffu, S0, off);
        S1 += __shfl_xor_sync(0xffffffffu, S1, off);
        S2 += __shfl_xor_sync(0xffffffffu, S2, off);
        S3 += __shfl_xor_sync(0xffffffffu, S3, off);
    }

    __shared__ float pE[8][16], pS[8][16];
    const int warp = tid >> 5;
    const int lane = tid & 31;
    if (lane < 4) {
        *(float4*)&pE[warp][lane * 4] = make_float4(E0, E1, E2, E3);
        *(float4*)&pS[warp][lane * 4] = make_float4(S0, S1, S2, S3);
    }
    __syncthreads();

    if (tid < 16) {
        float Et = 0.0f, St = 0.0f;
        #pragma unroll
        for (int w = 0; w < 8; w++) { Et += pE[w][tid]; St += pS[w][tid]; }
        float s = St / Et;
        g_s[blk * OO + tid] = s;

        float q = s * s;
        q += __shfl_xor_sync(0x0000ffffu, q, 1);
        q += __shfl_xor_sync(0x0000ffffu, q, 2);
        q += __shfl_xor_sync(0x0000ffffu, q, 4);
        q += __shfl_xor_sync(0x0000ffffu, q, 8);
        if (tid == 0) atomicAdd(&g_n2[t], q);
    }
}

// ---------------------------------------------------------------------------
__global__ __launch_bounds__(256)
void final_kernel(float* __restrict__ out) {
    int i = blockIdx.x * blockDim.x + threadIdx.x;
    if (i < S_ELEMS) {
        float n2 = g_n2[2];
        float sc = sqrtf(n2) / (1.0f + n2);
        out[i] = sc * g_s[i];
    }
}

// ---------------------------------------------------------------------------
extern "C" void kernel_launch(void* const* d_in, const int* in_sizes, int n_in,
                              void* d_out, int out_size) {
    const float* x = (const float*)d_in[0];   // [128][1152][8]
    const float* W = (const float*)d_in[1];   // [10][1152][8][16]
    float* out = (float*)d_out;               // [10][128][1][1][16]

    gemm_kernel<<<dim3(RR / RB, CC), 256>>>(x, W);
    mean_kernel<<<CC * BB, 256>>>();
    iter_kernel<<<CC * BB, 256>>>(1);
    iter_kernel<<<CC * BB, 256>>>(2);
    final_kernel<<<(S_ELEMS + 255) / 256, 256>>>(out);
}